// round 3
// baseline (speedup 1.0000x reference)
#include <cuda_runtime.h>
#include <math.h>
#include <stdint.h>

#define TT 512
#define DD 512
#define HH 1024
#define VV 8192
#define BB 16
#define BLANKTOK 8191
#define NEGF (-99999.0f)
#define EXPANDF 10.0f
#define NBLK 128
#define NTHR 256

// strides (floats) for smem activation tiles, chosen so 4*stride % 32 == 8 (bank-spread)
#define JSTRIDE 1026
#define LSTRIDE 2050
#define DYN_SMEM (16 * LSTRIDE * 4)   // 131200 bytes

// ---------------- device globals (no runtime alloc) ----------------
__device__ __align__(16) float g_enc[TT * HH];
__device__ __align__(16) float g_logits[BB * VV];
__device__ float g_m[BB], g_lz[BB], g_thr[BB], g_blanklp[BB];
__device__ float g_scores2[2][BB];
__device__ __align__(16) float g_h[2][BB * HH];
__device__ __align__(16) float g_c[2][BB * HH];
__device__ int g_tokens[2][BB * TT];
__device__ unsigned long long g_part[NBLK * BB];
__device__ __align__(16) float g_gates[BB * 4 * HH];
__device__ float g_g0[4 * HH];
__device__ unsigned g_bar_gen;
__device__ unsigned g_bar_cnt;

// ---------------- helpers ----------------
__device__ __forceinline__ float sigf(float x) {
    return (float)(1.0 / (1.0 + exp(-(double)x)));   // double: proven numerics (R1 passed)
}
__device__ __forceinline__ float tanh_acc(float x) {
    return (float)tanh((double)x);
}
__device__ __forceinline__ unsigned ordf(float f) {
    unsigned u = __float_as_uint(f);
    return (u & 0x80000000u) ? ~u : (u | 0x80000000u);
}
__device__ __forceinline__ float unordf(unsigned s) {
    return (s & 0x80000000u) ? __uint_as_float(s & 0x7FFFFFFFu) : __uint_as_float(~s);
}
__device__ __forceinline__ unsigned long long mkkey(float v, unsigned idx) {
    return ((unsigned long long)ordf(v) << 32) | (unsigned long long)(0xFFFFFFFFu - idx);
}

// grid-wide barrier: all NBLK blocks co-resident (1 block/SM via smem footprint)
__device__ __forceinline__ void gridbar() {
    __syncthreads();
    if (threadIdx.x == 0) {
        __threadfence();
        unsigned gen = *(volatile unsigned*)&g_bar_gen;
        unsigned a = atomicAdd(&g_bar_cnt, 1u);
        if (a == NBLK - 1u) {
            g_bar_cnt = 0u;
            __threadfence();
            *(volatile unsigned*)&g_bar_gen = gen + 1u;
        } else {
            while (*(volatile unsigned*)&g_bar_gen == gen) { __nanosleep(32); }
            __threadfence();
        }
    }
    __syncthreads();
}

// ---------------- the persistent kernel ----------------
__global__ void __launch_bounds__(NTHR, 1)
rnnt_persist(const float* __restrict__ inp,  const float* __restrict__ encW,
             const float* __restrict__ encb, const float* __restrict__ embed,
             const float* __restrict__ Wx,   const float* __restrict__ Wh,
             const float* __restrict__ blstm,const float* __restrict__ jW,
             const float* __restrict__ jb,   float* __restrict__ out) {
    extern __shared__ unsigned char smraw[];
    float* sact = (float*)smraw;                         // act tiles (aliased)
    unsigned long long* skeys = (unsigned long long*)smraw;  // topk keys (aliased)
    float* sred4 = (float*)smraw;                        // gemm reduction buf (aliased)

    __shared__ float xr[DD];
    __shared__ float s_m[BB], s_lz[BB], s_thr[BB], s_sc[BB];
    __shared__ int s_isblank[BB], s_bsel[BB], s_nsel[BB], s_nbtok[BB], s_nbhypo[BB];
    __shared__ float s_nbsc[BB];
    __shared__ unsigned s_nbid[BB];
    __shared__ float r1[NTHR], r2[NTHR], r3[NTHR];
    __shared__ double dred[NTHR];
    __shared__ unsigned long long wsm[8], s_winner;
    __shared__ float nh_s[BB][8], nc_s[BB][8];

    const int tid = threadIdx.x;
    const int blk = blockIdx.x;

    // ================= prologue =================
    // phA: enc = input @ enc_W + enc_b
    for (int t = blk; t < TT; t += NBLK) {
        for (int i = tid; i < DD; i += NTHR) xr[i] = inp[t * DD + i];
        __syncthreads();
        int col = tid * 4;
        float4 acc = {0.f, 0.f, 0.f, 0.f};
#pragma unroll 4
        for (int k = 0; k < DD; k++) {
            float4 w = *(const float4*)&encW[(size_t)k * HH + col];
            float a = xr[k];
            acc.x += a * w.x; acc.y += a * w.y; acc.z += a * w.z; acc.w += a * w.w;
        }
        float4 bv = *(const float4*)&encb[col];
        acc.x += bv.x; acc.y += bv.y; acc.z += bv.z; acc.w += bv.w;
        *(float4*)&g_enc[(size_t)t * HH + col] = acc;
        __syncthreads();
    }
    gridbar();
    // phB: g0 = embed[BLANK] @ Wx + b ; init tokens/scores
    if (blk < 16) {
        int col = blk * NTHR + tid;   // 4096
        float acc = 0.f;
        const float* er = &embed[(size_t)BLANKTOK * HH];
#pragma unroll 4
        for (int k = 0; k < HH; k++) acc += er[k] * Wx[(size_t)k * 4 * HH + col];
        g_g0[col] = acc + blstm[col];
    } else if (blk < 48) {
        int e = (blk - 16) * NTHR + tid;   // 8192
        g_tokens[0][e] = BLANKTOK;
    } else if (blk == 48 && tid < BB) {
        g_scores2[0][tid] = (tid == 0) ? 0.f : -1000000000.0f;
    }
    gridbar();
    // phC: h0, c0 broadcast to all beams
    if (blk < 4) {
        int u = blk * NTHR + tid;
        float gi = g_g0[u], gg = g_g0[2 * HH + u], go = g_g0[3 * HH + u];
        float c0 = sigf(gi) * tanh_acc(gg);
        float h0 = sigf(go) * tanh_acc(c0);
        for (int b = 0; b < BB; b++) {
            g_h[0][b * HH + u] = h0;
            g_c[0][b * HH + u] = c0;
        }
    }
    gridbar();

    // ================= main loop =================
    for (int t = 0; t < TT; t++) {
        const int par = t & 1, np = par ^ 1;

        // ---- ph1: joint GEMM: logits = relu(enc_t + h) @ jW + jb ----
        {
            const float* hs = g_h[par];
            const float* et = &g_enc[(size_t)t * HH];
            for (int idx = tid; idx < BB * HH; idx += NTHR) {
                int k = idx & (HH - 1), row = idx >> 10;
                float v = et[k] + hs[row * HH + k];
                sact[row * JSTRIDE + k] = v > 0.f ? v : 0.f;
            }
            __syncthreads();
            int quad = tid & 15, rg = (tid >> 4) & 3, kc = tid >> 6;
            int col = blk * 64 + quad * 4;
            const float* a0p = sact + (rg * 4 + 0) * JSTRIDE;
            const float* a1p = sact + (rg * 4 + 1) * JSTRIDE;
            const float* a2p = sact + (rg * 4 + 2) * JSTRIDE;
            const float* a3p = sact + (rg * 4 + 3) * JSTRIDE;
            float4 c0 = {0,0,0,0}, c1 = c0, c2 = c0, c3 = c0;
            int k0 = kc * 256;
#pragma unroll 4
            for (int k = k0; k < k0 + 256; k++) {
                float4 w = *(const float4*)&jW[(size_t)k * VV + col];
                float x0 = a0p[k], x1 = a1p[k], x2 = a2p[k], x3 = a3p[k];
                c0.x += x0*w.x; c0.y += x0*w.y; c0.z += x0*w.z; c0.w += x0*w.w;
                c1.x += x1*w.x; c1.y += x1*w.y; c1.z += x1*w.z; c1.w += x1*w.w;
                c2.x += x2*w.x; c2.y += x2*w.y; c2.z += x2*w.z; c2.w += x2*w.w;
                c3.x += x3*w.x; c3.y += x3*w.y; c3.z += x3*w.z; c3.w += x3*w.w;
            }
            __syncthreads();   // act dead; alias as reduction buffer
            int unit = rg * 16 + quad;
            int rb = (kc * 64 + unit) * 16;
            *(float4*)&sred4[rb + 0] = c0; *(float4*)&sred4[rb + 4]  = c1;
            *(float4*)&sred4[rb + 8] = c2; *(float4*)&sred4[rb + 12] = c3;
            __syncthreads();
            if (kc == 0) {   // tid < 64
                for (int r = 0; r < 4; r++) {
                    int row = rg * 4 + r;
                    for (int ci = 0; ci < 4; ci++) {
                        float s = sred4[(0 * 64 + unit) * 16 + r * 4 + ci]
                                + sred4[(1 * 64 + unit) * 16 + r * 4 + ci]
                                + sred4[(2 * 64 + unit) * 16 + r * 4 + ci]
                                + sred4[(3 * 64 + unit) * 16 + r * 4 + ci];
                        g_logits[row * VV + col + ci] = s + jb[col + ci];
                    }
                }
            }
        }
        gridbar();

        // ---- ph2: row stats ----
        if (blk < BB) {
            const float* row = &g_logits[blk * VV];
            float m = -1e30f, mn = -1e30f, mf = -1e30f;
            for (int v = tid; v < VV; v += NTHR) {
                float x = row[v];
                m = fmaxf(m, x);
                if (v >= 4 && v < VV - 1) mn = fmaxf(mn, x);
                if (v < 4) mf = fmaxf(mf, x);
            }
            r1[tid] = m; r2[tid] = mn; r3[tid] = mf; __syncthreads();
            for (int s = 128; s > 0; s >>= 1) {
                if (tid < s) {
                    r1[tid] = fmaxf(r1[tid], r1[tid + s]);
                    r2[tid] = fmaxf(r2[tid], r2[tid + s]);
                    r3[tid] = fmaxf(r3[tid], r3[tid + s]);
                }
                __syncthreads();
            }
            m = r1[0]; mn = r2[0]; mf = r3[0]; __syncthreads();
            double z = 0.0;
            for (int v = tid; v < VV; v += NTHR) z += (double)expf(row[v] - m);
            dred[tid] = z; __syncthreads();
            for (int s = 128; s > 0; s >>= 1) {
                if (tid < s) dred[tid] += dred[tid + s];
                __syncthreads();
            }
            if (tid == 0) {
                float lz = (float)log(dred[0]);
                g_m[blk] = m; g_lz[blk] = lz;
                float t1 = (mn - m) - lz;
                float t2 = ((mf - m) - lz) + NEGF;
                g_thr[blk] = fmaxf(t1, t2) - EXPANDF;
                g_blanklp[blk] = (row[VV - 1] - m) - lz;
            }
        }
        gridbar();

        // ---- ph3: candidates + per-block top-16 ----
        {
            if (tid < BB) {
                s_m[tid] = g_m[tid]; s_lz[tid] = g_lz[tid];
                s_thr[tid] = g_thr[tid]; s_sc[tid] = g_scores2[par][tid];
            }
            __syncthreads();
            int v0 = blk * 64;
#pragma unroll
            for (int i = 0; i < 4; i++) {
                int e = tid + i * NTHR;
                int b = e >> 6, vo = e & 63, v = v0 + vo;
                unsigned long long key = 0ULL;
                if (v < VV - 1) {
                    float lp = (g_logits[b * VV + v] - s_m[b]) - s_lz[b];
                    if (v < 4) lp += NEGF;
                    float nb = (lp > s_thr[b]) ? lp : NEGF;
                    key = mkkey(s_sc[b] + nb, (unsigned)(b * (VV - 1) + v));
                }
                skeys[e] = key;
            }
            __syncthreads();
            for (int r = 0; r < BB; r++) {
                unsigned long long loc = 0ULL;
#pragma unroll
                for (int i = 0; i < 4; i++) {
                    unsigned long long k = skeys[tid + i * NTHR];
                    if (k > loc) loc = k;
                }
                for (int off = 16; off; off >>= 1) {
                    unsigned long long o = __shfl_down_sync(0xffffffffu, loc, off);
                    if (o > loc) loc = o;
                }
                if ((tid & 31) == 0) wsm[tid >> 5] = loc;
                __syncthreads();
                if (tid == 0) {
                    unsigned long long w = wsm[0];
                    for (int i = 1; i < 8; i++) if (wsm[i] > w) w = wsm[i];
                    s_winner = w;
                    g_part[blk * BB + r] = w;
                }
                __syncthreads();
                unsigned long long w = s_winner;
#pragma unroll
                for (int i = 0; i < 4; i++)
                    if (skeys[tid + i * NTHR] == w) skeys[tid + i * NTHR] = 0ULL;
                __syncthreads();
            }
        }
        gridbar();

        // ---- ph4: replicated select + LSTM GEMM ----
        {
            for (int i = tid; i < NBLK * BB; i += NTHR) skeys[i] = g_part[i];
            __syncthreads();
            for (int r = 0; r < BB; r++) {
                unsigned long long loc = 0ULL;
#pragma unroll
                for (int i = 0; i < 8; i++) {
                    unsigned long long k = skeys[tid + i * NTHR];
                    if (k > loc) loc = k;
                }
                for (int off = 16; off; off >>= 1) {
                    unsigned long long o = __shfl_down_sync(0xffffffffu, loc, off);
                    if (o > loc) loc = o;
                }
                if ((tid & 31) == 0) wsm[tid >> 5] = loc;
                __syncthreads();
                if (tid == 0) {
                    unsigned long long w = wsm[0];
                    for (int i = 1; i < 8; i++) if (wsm[i] > w) w = wsm[i];
                    s_winner = w;
                    s_nbsc[r] = unordf((unsigned)(w >> 32));
                    s_nbid[r] = 0xFFFFFFFFu - (unsigned)(w & 0xFFFFFFFFu);
                }
                __syncthreads();
                unsigned long long w = s_winner;
#pragma unroll
                for (int i = 0; i < 8; i++)
                    if (skeys[tid + i * NTHR] == w) skeys[tid + i * NTHR] = 0ULL;
                __syncthreads();
            }
            if (tid == 0) {
                float allv[2 * BB];
                unsigned long long allk[2 * BB];
                for (int i = 0; i < BB; i++) {
                    float bs = g_scores2[par][i] + g_blanklp[i];
                    allv[i] = bs; allk[i] = mkkey(bs, (unsigned)i);
                }
                for (int i = 0; i < BB; i++) {
                    allv[BB + i] = s_nbsc[i];
                    allk[BB + i] = mkkey(s_nbsc[i], (unsigned)(BB + i));
                }
                for (int r = 0; r < BB; r++) {
                    int best = 0;
                    for (int i = 1; i < 2 * BB; i++) if (allk[i] > allk[best]) best = i;
                    float ns = allv[best];
                    allk[best] = 0ULL;
                    s_isblank[r] = (best < BB) ? 1 : 0;
                    s_bsel[r] = (best < BB) ? best : (BB - 1);
                    int n2 = best - BB;
                    if (n2 < 0) n2 = 0;
                    if (n2 > BB - 1) n2 = BB - 1;
                    s_nsel[r] = n2;
                    if (blk == 0) g_scores2[np][r] = ns;
                }
                for (int j = 0; j < BB; j++) {
                    s_nbhypo[j] = (int)(s_nbid[j] / (VV - 1));
                    s_nbtok[j]  = (int)(s_nbid[j] % (VV - 1));
                }
            }
            __syncthreads();
            // LSTM act tile: rows = 16 new hypos, k2<1024 -> embed, else h
            const float* hs = g_h[par];
            for (int idx = tid; idx < BB * 2 * HH; idx += NTHR) {
                int k2 = idx & (2 * HH - 1), row = idx >> 11;
                float v = (k2 < HH) ? embed[(size_t)s_nbtok[row] * HH + k2]
                                    : hs[s_nbhypo[row] * HH + (k2 - HH)];
                sact[row * LSTRIDE + k2] = v;
            }
            __syncthreads();
            int quad = tid & 7, rg = (tid >> 3) & 3, kc = tid >> 5;  // kc 0..7
            int col = blk * 32 + quad * 4;
            const float* W = (kc < 4) ? Wx : Wh;
            int kb = (kc < 4) ? kc * 256 : (kc - 4) * 256;
            int k2b = kc * 256;
            const float* a0p = sact + (rg * 4 + 0) * LSTRIDE + k2b;
            const float* a1p = sact + (rg * 4 + 1) * LSTRIDE + k2b;
            const float* a2p = sact + (rg * 4 + 2) * LSTRIDE + k2b;
            const float* a3p = sact + (rg * 4 + 3) * LSTRIDE + k2b;
            float4 c0 = {0,0,0,0}, c1 = c0, c2 = c0, c3 = c0;
#pragma unroll 4
            for (int kk = 0; kk < 256; kk++) {
                float4 w = *(const float4*)&W[(size_t)(kb + kk) * (4 * HH) + col];
                float x0 = a0p[kk], x1 = a1p[kk], x2 = a2p[kk], x3 = a3p[kk];
                c0.x += x0*w.x; c0.y += x0*w.y; c0.z += x0*w.z; c0.w += x0*w.w;
                c1.x += x1*w.x; c1.y += x1*w.y; c1.z += x1*w.z; c1.w += x1*w.w;
                c2.x += x2*w.x; c2.y += x2*w.y; c2.z += x2*w.z; c2.w += x2*w.w;
                c3.x += x3*w.x; c3.y += x3*w.y; c3.z += x3*w.z; c3.w += x3*w.w;
            }
            __syncthreads();
            int unit = rg * 8 + quad;   // 32 units
            int rb = (kc * 32 + unit) * 16;
            *(float4*)&sred4[rb + 0] = c0; *(float4*)&sred4[rb + 4]  = c1;
            *(float4*)&sred4[rb + 8] = c2; *(float4*)&sred4[rb + 12] = c3;
            __syncthreads();
            if (kc == 0) {   // tid < 32
                for (int r = 0; r < 4; r++) {
                    int row = rg * 4 + r;
                    for (int ci = 0; ci < 4; ci++) {
                        float s = 0.f;
                        for (int c8 = 0; c8 < 8; c8++)
                            s += sred4[(c8 * 32 + unit) * 16 + r * 4 + ci];
                        g_gates[row * 4 * HH + col + ci] = s + blstm[col + ci];
                    }
                }
            }
        }
        gridbar();

        // ---- ph5: LSTM elementwise + apply selection ----
        {
            int ub = blk * 8;   // 128 blocks * 8 = 1024 units
            if (tid < 128) {
                int j = tid >> 3, uo = tid & 7, u = ub + uo;
                float gi = g_gates[j * 4096 + u];
                float gf = g_gates[j * 4096 + 1024 + u];
                float gg = g_gates[j * 4096 + 2048 + u];
                float go = g_gates[j * 4096 + 3072 + u];
                float cp = g_c[par][s_nbhypo[j] * HH + u];
                float cc = sigf(gf) * cp + sigf(gi) * tanh_acc(gg);
                nc_s[j][uo] = cc;
                nh_s[j][uo] = sigf(go) * tanh_acc(cc);
            }
            __syncthreads();
            if (tid < 128) {
                int i = tid >> 3, uo = tid & 7, u = ub + uo;
                float hn, cn;
                if (s_isblank[i]) {
                    hn = g_h[par][s_bsel[i] * HH + u];
                    cn = g_c[par][s_bsel[i] * HH + u];
                } else {
                    int ns = s_nsel[i];
                    hn = nh_s[ns][uo]; cn = nc_s[ns][uo];
                }
                g_h[np][i * HH + u] = hn;
                g_c[np][i * HH + u] = cn;
            }
            if (tid < 64) {
                int i = tid >> 2, sl = blk * 4 + (tid & 3);
                int tok;
                if (s_isblank[i]) {
                    tok = g_tokens[par][s_bsel[i] * TT + sl];
                } else {
                    int ns = s_nsel[i];
                    tok = (sl == t) ? s_nbtok[ns] : g_tokens[par][s_nbhypo[ns] * TT + sl];
                }
                g_tokens[np][i * TT + sl] = tok;
            }
        }
        gridbar();
    }

    // ================= epilogue: write output =================
    if (blk == 0) {
        for (int e = tid; e < BB; e += NTHR) out[e] = g_scores2[0][e];
        for (int e = tid; e < BB * TT; e += NTHR) out[BB + e] = (float)g_tokens[0][e];
    }
}

// ---------------- host ----------------
extern "C" void kernel_launch(void* const* d_in, const int* in_sizes, int n_in,
                              void* d_out, int out_size) {
    const float* input   = (const float*)d_in[0];
    const float* enc_W   = (const float*)d_in[1];
    const float* enc_b   = (const float*)d_in[2];
    const float* embed   = (const float*)d_in[3];
    const float* Wx      = (const float*)d_in[4];
    const float* Wh      = (const float*)d_in[5];
    const float* b_lstm  = (const float*)d_in[6];
    const float* joint_W = (const float*)d_in[7];
    const float* joint_b = (const float*)d_in[8];
    (void)in_sizes; (void)n_in; (void)out_size;

    cudaFuncSetAttribute(rnnt_persist, cudaFuncAttributeMaxDynamicSharedMemorySize, DYN_SMEM);
    rnnt_persist<<<NBLK, NTHR, DYN_SMEM>>>(input, enc_W, enc_b, embed, Wx, Wh,
                                           b_lstm, joint_W, joint_b, (float*)d_out);
}

// round 4
// speedup vs baseline: 1.3963x; 1.3963x over previous
#include <cuda_runtime.h>
#include <math.h>
#include <stdint.h>

#define TT 512
#define DD 512
#define HH 1024
#define VV 8192
#define BB 16
#define BLANKTOK 8191
#define NEGF (-99999.0f)
#define EXPANDF 10.0f
#define NBLK 128
#define NTHR 512
#define JP 1025                       // packed-act row stride, in float2/u64 units
#define DYN_SMEM (16 * JP * 8)        // 131200 bytes

// ---------------- device globals (no runtime alloc) ----------------
__device__ __align__(16) float g_enc[TT * HH];
__device__ float g_pmax[BB * NBLK];
__device__ float g_pnb[BB * NBLK];
__device__ float g_mf[BB];
__device__ float g_blanklogit[BB];
__device__ double g_psum[BB * NBLK];
__device__ float g_scores2[2][BB];
__device__ __align__(16) float g_h[2][BB * HH];
__device__ __align__(16) float g_c[2][BB * HH];
__device__ int g_tokens[2][BB * TT];
__device__ unsigned long long g_part[NBLK * BB];
__device__ float g_g0[4 * HH];
__device__ unsigned g_bar_gen;
__device__ unsigned g_bar_cnt;

// ---------------- helpers ----------------
__device__ __forceinline__ float sigf(float x) {
    return (float)(1.0 / (1.0 + exp(-(double)x)));   // proven numerics (R3 passed)
}
__device__ __forceinline__ float tanh_acc(float x) {
    return (float)tanh((double)x);
}
__device__ __forceinline__ unsigned ordf(float f) {
    unsigned u = __float_as_uint(f);
    return (u & 0x80000000u) ? ~u : (u | 0x80000000u);
}
__device__ __forceinline__ float unordf(unsigned s) {
    return (s & 0x80000000u) ? __uint_as_float(s & 0x7FFFFFFFu) : __uint_as_float(~s);
}
__device__ __forceinline__ unsigned long long mkkey(float v, unsigned idx) {
    return ((unsigned long long)ordf(v) << 32) | (unsigned long long)(0xFFFFFFFFu - idx);
}
// packed f32x2 fma: d.lo += a.lo*b.lo ; d.hi += a.hi*b.hi  (IEEE fp32 FMA per lane)
__device__ __forceinline__ void ffma2(unsigned long long& d, unsigned long long a,
                                      unsigned long long b) {
    asm("fma.rn.f32x2 %0, %1, %2, %0;" : "+l"(d) : "l"(a), "l"(b));
}
__device__ __forceinline__ unsigned long long pk2(float x) {
    unsigned long long r;
    asm("mov.b64 %0, {%1, %1};" : "=l"(r) : "r"(__float_as_uint(x)));
    return r;
}
__device__ __forceinline__ float2 up2(unsigned long long p) {
    unsigned lo, hi;
    asm("mov.b64 {%0, %1}, %2;" : "=r"(lo), "=r"(hi) : "l"(p));
    float2 f;
    f.x = __uint_as_float(lo); f.y = __uint_as_float(hi);
    return f;
}
__device__ __forceinline__ void gridbar() {
    __syncthreads();
    if (threadIdx.x == 0) {
        __threadfence();
        unsigned gen = *(volatile unsigned*)&g_bar_gen;
        unsigned a = atomicAdd(&g_bar_cnt, 1u);
        if (a == NBLK - 1u) {
            g_bar_cnt = 0u;
            __threadfence();
            *(volatile unsigned*)&g_bar_gen = gen + 1u;
        } else {
            while (*(volatile unsigned*)&g_bar_gen == gen) { __nanosleep(32); }
            __threadfence();
        }
    }
    __syncthreads();
}

// ---------------- the persistent kernel ----------------
__global__ void __launch_bounds__(NTHR, 1)
rnnt_persist(const float* __restrict__ inp,  const float* __restrict__ encW,
             const float* __restrict__ encb, const float* __restrict__ embed,
             const float* __restrict__ Wx,   const float* __restrict__ Wh,
             const float* __restrict__ blstm,const float* __restrict__ jW,
             const float* __restrict__ jb,   float* __restrict__ out) {
    extern __shared__ unsigned long long smp[];   // packed act / keys / reduction (aliased)

    __shared__ float xr[DD];
    __shared__ float s_logits[BB][65];
    __shared__ float s_gates[BB][33];
    __shared__ float s_m[BB], s_nbm[BB], s_lz[BB], s_thr[BB], s_blk[BB], s_sc[BB];
    __shared__ float s_newsc[BB], s_nbsc[BB];
    __shared__ int s_nbhypo[BB], s_nbtok[BB], s_isblank[BB], s_bsel[BB], s_nsel[BB];
    __shared__ unsigned long long s_stk[256];
    __shared__ float nh_s[BB][8], nc_s[BB][8];

    const int tid = threadIdx.x;
    const int blk = blockIdx.x;
    const int lane = tid & 31;
    const int wrp = tid >> 5;   // 0..15 == beam row for warp-parallel phases

    // ================= prologue =================
    for (int t0 = blk; t0 < TT; t0 += NBLK) {
        for (int i = tid; i < DD; i += NTHR) xr[i] = inp[t0 * DD + i];
        __syncthreads();
        int col = tid * 2;
        float a0 = 0.f, a1 = 0.f;
#pragma unroll 4
        for (int k = 0; k < DD; k++) {
            float2 w = *(const float2*)&encW[(size_t)k * HH + col];
            a0 += xr[k] * w.x; a1 += xr[k] * w.y;
        }
        g_enc[(size_t)t0 * HH + col]     = a0 + encb[col];
        g_enc[(size_t)t0 * HH + col + 1] = a1 + encb[col + 1];
        __syncthreads();
    }
    gridbar();
    if (blk < 8) {
        int col = blk * NTHR + tid;   // 4096
        float acc = 0.f;
        const float* er = &embed[(size_t)BLANKTOK * HH];
#pragma unroll 4
        for (int k = 0; k < HH; k++) acc += er[k] * Wx[(size_t)k * 4 * HH + col];
        g_g0[col] = acc + blstm[col];
    } else if (blk < 24) {
        int e = (blk - 8) * NTHR + tid;   // 8192
        g_tokens[0][e] = BLANKTOK;
    } else if (blk == 24 && tid < BB) {
        g_scores2[0][tid] = (tid == 0) ? 0.f : -1000000000.0f;
    }
    gridbar();
    if (blk < 2) {
        int u = blk * NTHR + tid;
        float gi = g_g0[u], gg = g_g0[2 * HH + u], go = g_g0[3 * HH + u];
        float c0 = sigf(gi) * tanh_acc(gg);
        float h0 = sigf(go) * tanh_acc(c0);
        for (int b = 0; b < BB; b++) {
            g_h[0][b * HH + u] = h0;
            g_c[0][b * HH + u] = c0;
        }
    }
    gridbar();

    // ================= main loop =================
    for (int t = 0; t < TT; t++) {
        const int par = t & 1, np = par ^ 1;

        // ---- ph1: joint GEMM (packed f32x2) + logits tile + partial stats ----
        {
            const float* hs = g_h[par];
            const float* et = &g_enc[(size_t)t * HH];
            float e0 = et[tid], e1 = et[tid + 512];
#pragma unroll
            for (int r = 0; r < BB; r++) {
                float v0 = e0 + hs[r * HH + tid];        v0 = v0 > 0.f ? v0 : 0.f;
                float v1 = e1 + hs[r * HH + tid + 512];  v1 = v1 > 0.f ? v1 : 0.f;
                smp[r * JP + tid]       = pk2(v0);
                smp[r * JP + tid + 512] = pk2(v1);
            }
            __syncthreads();
            int quad = tid & 15, rg = (tid >> 4) & 3, kc = tid >> 6;   // kc 0..7
            int col = blk * 64 + quad * 4;
            const ulonglong2* wk = (const ulonglong2*)(jW + (size_t)(kc * 128) * VV + col);
            const unsigned long long* a0 = smp + (rg * 4 + 0) * JP + kc * 128;
            const unsigned long long* a1 = a0 + JP;
            const unsigned long long* a2 = a1 + JP;
            const unsigned long long* a3 = a2 + JP;
            unsigned long long c00=0,c01=0,c10=0,c11=0,c20=0,c21=0,c30=0,c31=0;
#pragma unroll 4
            for (int kk = 0; kk < 128; kk++) {
                ulonglong2 w = *wk; wk += VV / 4;
                unsigned long long x0 = a0[kk], x1 = a1[kk], x2 = a2[kk], x3 = a3[kk];
                ffma2(c00, x0, w.x); ffma2(c01, x0, w.y);
                ffma2(c10, x1, w.x); ffma2(c11, x1, w.y);
                ffma2(c20, x2, w.x); ffma2(c21, x2, w.y);
                ffma2(c30, x3, w.x); ffma2(c31, x3, w.y);
            }
            __syncthreads();   // act dead; alias as partial buffer
            float* sred = (float*)smp;
            int unit = rg * 16 + quad;   // 0..63
            float2 f00=up2(c00), f01=up2(c01), f10=up2(c10), f11=up2(c11);
            float2 f20=up2(c20), f21=up2(c21), f30=up2(c30), f31=up2(c31);
            float4* dst = (float4*)&sred[(kc * 64 + unit) * 16];
            dst[0] = make_float4(f00.x, f00.y, f01.x, f01.y);
            dst[1] = make_float4(f10.x, f10.y, f11.x, f11.y);
            dst[2] = make_float4(f20.x, f20.y, f21.x, f21.y);
            dst[3] = make_float4(f30.x, f30.y, f31.x, f31.y);
            __syncthreads();
#pragma unroll
            for (int oo = tid; oo < 1024; oo += NTHR) {
                int unit2 = oo >> 4, rr = (oo >> 2) & 3, ci = oo & 3;
                float s = 0.f;
#pragma unroll
                for (int k8 = 0; k8 < 8; k8++)
                    s += sred[(k8 * 64 + unit2) * 16 + rr * 4 + ci];
                int rg2 = unit2 >> 4, q2 = unit2 & 15;
                s_logits[rg2 * 4 + rr][q2 * 4 + ci] = s + jb[blk * 64 + q2 * 4 + ci];
            }
            __syncthreads();
            // partial row stats (warp wrp = beam row wrp)
            float x0 = s_logits[wrp][lane], x1 = s_logits[wrp][lane + 32];
            float pm = fmaxf(x0, x1);
            float nb0 = (blk == 0 && lane < 4) ? -1e30f : x0;
            float nb1 = (blk == NBLK - 1 && lane == 31) ? -1e30f : x1;
            float pn = fmaxf(nb0, nb1);
            for (int off = 16; off; off >>= 1) {
                pm = fmaxf(pm, __shfl_xor_sync(0xffffffffu, pm, off));
                pn = fmaxf(pn, __shfl_xor_sync(0xffffffffu, pn, off));
            }
            if (lane == 0) {
                g_pmax[wrp * NBLK + blk] = pm;
                g_pnb[wrp * NBLK + blk]  = pn;
                if (blk == 0)
                    g_mf[wrp] = fmaxf(fmaxf(s_logits[wrp][0], s_logits[wrp][1]),
                                      fmaxf(s_logits[wrp][2], s_logits[wrp][3]));
                if (blk == NBLK - 1) g_blanklogit[wrp] = s_logits[wrp][63];
            }
        }
        gridbar();

        // ---- ph2: combine maxes + distributed exp partial sums ----
        {
            const float4* pmv = (const float4*)&g_pmax[wrp * NBLK];
            float4 q = pmv[lane];
            float pm = fmaxf(fmaxf(q.x, q.y), fmaxf(q.z, q.w));
            const float4* pnv = (const float4*)&g_pnb[wrp * NBLK];
            float4 q2 = pnv[lane];
            float pn = fmaxf(fmaxf(q2.x, q2.y), fmaxf(q2.z, q2.w));
            for (int off = 16; off; off >>= 1) {
                pm = fmaxf(pm, __shfl_xor_sync(0xffffffffu, pm, off));
                pn = fmaxf(pn, __shfl_xor_sync(0xffffffffu, pn, off));
            }
            if (lane == 0) { s_m[wrp] = pm; s_nbm[wrp] = pn; }
            float m = pm;   // all lanes hold the full max
            float xx0 = s_logits[wrp][lane], xx1 = s_logits[wrp][lane + 32];
            double d = (double)expf(xx0 - m) + (double)expf(xx1 - m);
            for (int off = 16; off; off >>= 1)
                d += __shfl_down_sync(0xffffffffu, d, off);
            if (lane == 0) g_psum[wrp * NBLK + blk] = d;
        }
        gridbar();

        // ---- ph3: logZ + candidates + per-block top-16 ----
        {
            if (tid < BB) s_sc[tid] = g_scores2[par][tid];
            {
                const double* ps = &g_psum[wrp * NBLK];
                double s = ps[lane * 4 + 0] + ps[lane * 4 + 1]
                         + ps[lane * 4 + 2] + ps[lane * 4 + 3];
                for (int off = 16; off; off >>= 1)
                    s += __shfl_down_sync(0xffffffffu, s, off);
                if (lane == 0) {
                    float lz = (float)log(s);
                    float m = s_m[wrp];
                    s_lz[wrp] = lz;
                    float t1 = (s_nbm[wrp] - m) - lz;
                    float t2 = ((g_mf[wrp] - m) - lz) + NEGF;
                    s_thr[wrp] = fmaxf(t1, t2) - EXPANDF;
                    s_blk[wrp] = (g_blanklogit[wrp] - m) - lz;
                }
            }
            __syncthreads();
            float m = s_m[wrp], lz = s_lz[wrp], thr = s_thr[wrp], sc = s_sc[wrp];
            int c0 = lane, c1 = lane + 32;
            float x0 = s_logits[wrp][c0], x1 = s_logits[wrp][c1];
            float lp0 = (x0 - m) - lz;
            if (blk == 0 && c0 < 4) lp0 += NEGF;
            float lp1 = (x1 - m) - lz;
            float nb0 = lp0 > thr ? lp0 : NEGF;
            float nb1 = lp1 > thr ? lp1 : NEGF;
            int v0 = blk * 64 + c0, v1 = blk * 64 + c1;
            unsigned long long k0 = mkkey(sc + nb0, (unsigned)(wrp * (VV - 1) + v0));
            unsigned long long k1 = (v1 == VV - 1) ? 0ULL
                                  : mkkey(sc + nb1, (unsigned)(wrp * (VV - 1) + v1));
            // warp-local top-16 (no block syncs in rounds)
            for (int r = 0; r < BB; r++) {
                unsigned long long loc = k0 > k1 ? k0 : k1;
                for (int off = 16; off; off >>= 1) {
                    unsigned long long o = __shfl_xor_sync(0xffffffffu, loc, off);
                    if (o > loc) loc = o;
                }
                if (lane == r) s_stk[wrp * 16 + r] = loc;
                if (k0 == loc) k0 = 0ULL;
                if (k1 == loc) k1 = 0ULL;
            }
            __syncthreads();
            if (wrp == 0) {   // merge 256 -> 16
                unsigned long long kk[8];
#pragma unroll
                for (int j = 0; j < 8; j++) kk[j] = s_stk[lane + 32 * j];
                for (int r = 0; r < BB; r++) {
                    unsigned long long loc = kk[0];
#pragma unroll
                    for (int j = 1; j < 8; j++) if (kk[j] > loc) loc = kk[j];
                    for (int off = 16; off; off >>= 1) {
                        unsigned long long o = __shfl_xor_sync(0xffffffffu, loc, off);
                        if (o > loc) loc = o;
                    }
                    if (lane == r) g_part[blk * 16 + r] = loc;
#pragma unroll
                    for (int j = 0; j < 8; j++) if (kk[j] == loc) kk[j] = 0ULL;
                }
            }
        }
        gridbar();

        // ---- ph4: global merge + select + LSTM GEMM + elementwise + apply ----
        {
            {   // merge stage 1: warp wrp handles 128 keys
                unsigned long long kk[4];
#pragma unroll
                for (int j = 0; j < 4; j++) kk[j] = g_part[wrp * 128 + lane + 32 * j];
                for (int r = 0; r < BB; r++) {
                    unsigned long long loc = kk[0];
#pragma unroll
                    for (int j = 1; j < 4; j++) if (kk[j] > loc) loc = kk[j];
                    for (int off = 16; off; off >>= 1) {
                        unsigned long long o = __shfl_xor_sync(0xffffffffu, loc, off);
                        if (o > loc) loc = o;
                    }
                    if (lane == r) s_stk[wrp * 16 + r] = loc;
#pragma unroll
                    for (int j = 0; j < 4; j++) if (kk[j] == loc) kk[j] = 0ULL;
                }
            }
            __syncthreads();
            if (wrp == 0) {   // merge stage 2 + final 32-way select (replicated)
                unsigned long long kk[8];
#pragma unroll
                for (int j = 0; j < 8; j++) kk[j] = s_stk[lane + 32 * j];
                for (int r = 0; r < BB; r++) {
                    unsigned long long loc = kk[0];
#pragma unroll
                    for (int j = 1; j < 8; j++) if (kk[j] > loc) loc = kk[j];
                    for (int off = 16; off; off >>= 1) {
                        unsigned long long o = __shfl_xor_sync(0xffffffffu, loc, off);
                        if (o > loc) loc = o;
                    }
                    if (lane == r) {
                        s_nbsc[r] = unordf((unsigned)(loc >> 32));
                        unsigned id = 0xFFFFFFFFu - (unsigned)(loc & 0xFFFFFFFFu);
                        s_nbhypo[r] = (int)(id / (VV - 1));
                        s_nbtok[r]  = (int)(id % (VV - 1));
                    }
#pragma unroll
                    for (int j = 0; j < 8; j++) if (kk[j] == loc) kk[j] = 0ULL;
                }
                __syncwarp();
                float val = (lane < BB) ? (s_sc[lane] + s_blk[lane]) : s_nbsc[lane - BB];
                unsigned long long key = mkkey(val, (unsigned)lane);
                for (int r = 0; r < BB; r++) {
                    unsigned long long loc = key;
                    for (int off = 16; off; off >>= 1) {
                        unsigned long long o = __shfl_xor_sync(0xffffffffu, loc, off);
                        if (o > loc) loc = o;
                    }
                    unsigned idx = 0xFFFFFFFFu - (unsigned)(loc & 0xFFFFFFFFu);
                    if (lane == r) {
                        s_newsc[r] = unordf((unsigned)(loc >> 32));
                        s_isblank[r] = (idx < BB) ? 1 : 0;
                        s_bsel[r] = (idx < BB) ? (int)idx : (BB - 1);
                        int n2 = (int)idx - BB;
                        n2 = n2 < 0 ? 0 : (n2 > BB - 1 ? BB - 1 : n2);
                        s_nsel[r] = n2;
                    }
                    if (lane == (int)idx) key = 0ULL;
                }
            }
            __syncthreads();
            if (blk == 0 && tid < BB) g_scores2[np][tid] = s_newsc[tid];

            // --- LSTM GEMM: gates = embed[tok]@Wx + h[hypo]@Wh + b (two k-halves) ---
            int quad = tid & 7, rg = (tid >> 3) & 3, kc = tid >> 5;   // kc 0..15
            int gate = quad >> 1, hf = quad & 1;
            int gcol = gate * 1024 + blk * 8 + hf * 4;
            const unsigned long long* b0 = smp + (rg * 4 + 0) * JP + kc * 64;
            const unsigned long long* b1 = b0 + JP;
            const unsigned long long* b2 = b1 + JP;
            const unsigned long long* b3 = b2 + JP;
            unsigned long long c00=0,c01=0,c10=0,c11=0,c20=0,c21=0,c30=0,c31=0;
            // half A: embed rows
#pragma unroll
            for (int r = 0; r < BB; r++) {
                const float* er = &embed[(size_t)s_nbtok[r] * HH];
                smp[r * JP + tid]       = pk2(er[tid]);
                smp[r * JP + tid + 512] = pk2(er[tid + 512]);
            }
            __syncthreads();
            {
                const ulonglong2* wk =
                    (const ulonglong2*)(Wx + (size_t)(kc * 64) * (4 * HH) + gcol);
#pragma unroll 4
                for (int kk = 0; kk < 64; kk++) {
                    ulonglong2 w = *wk; wk += (4 * HH) / 4;
                    unsigned long long x0 = b0[kk], x1 = b1[kk], x2 = b2[kk], x3 = b3[kk];
                    ffma2(c00, x0, w.x); ffma2(c01, x0, w.y);
                    ffma2(c10, x1, w.x); ffma2(c11, x1, w.y);
                    ffma2(c20, x2, w.x); ffma2(c21, x2, w.y);
                    ffma2(c30, x3, w.x); ffma2(c31, x3, w.y);
                }
            }
            __syncthreads();
            // half B: h rows
            {
                const float* hs = g_h[par];
#pragma unroll
                for (int r = 0; r < BB; r++) {
                    const float* hr = &hs[s_nbhypo[r] * HH];
                    smp[r * JP + tid]       = pk2(hr[tid]);
                    smp[r * JP + tid + 512] = pk2(hr[tid + 512]);
                }
            }
            __syncthreads();
            {
                const ulonglong2* wk =
                    (const ulonglong2*)(Wh + (size_t)(kc * 64) * (4 * HH) + gcol);
#pragma unroll 4
                for (int kk = 0; kk < 64; kk++) {
                    ulonglong2 w = *wk; wk += (4 * HH) / 4;
                    unsigned long long x0 = b0[kk], x1 = b1[kk], x2 = b2[kk], x3 = b3[kk];
                    ffma2(c00, x0, w.x); ffma2(c01, x0, w.y);
                    ffma2(c10, x1, w.x); ffma2(c11, x1, w.y);
                    ffma2(c20, x2, w.x); ffma2(c21, x2, w.y);
                    ffma2(c30, x3, w.x); ffma2(c31, x3, w.y);
                }
            }
            __syncthreads();
            float* sred = (float*)smp;
            int unit = rg * 8 + quad;   // 0..31
            float2 f00=up2(c00), f01=up2(c01), f10=up2(c10), f11=up2(c11);
            float2 f20=up2(c20), f21=up2(c21), f30=up2(c30), f31=up2(c31);
            float4* dst = (float4*)&sred[(kc * 32 + unit) * 16];
            dst[0] = make_float4(f00.x, f00.y, f01.x, f01.y);
            dst[1] = make_float4(f10.x, f10.y, f11.x, f11.y);
            dst[2] = make_float4(f20.x, f20.y, f21.x, f21.y);
            dst[3] = make_float4(f30.x, f30.y, f31.x, f31.y);
            __syncthreads();
            {
                int oo = tid;   // 512 outputs
                int unit2 = oo >> 4, rr = (oo >> 2) & 3, ci = oo & 3;
                float s = 0.f;
#pragma unroll
                for (int k16 = 0; k16 < 16; k16++)
                    s += sred[(k16 * 32 + unit2) * 16 + rr * 4 + ci];
                int rg2 = unit2 >> 3, q2 = unit2 & 7;
                int row = rg2 * 4 + rr, lc = q2 * 4 + ci;
                int gc = (lc >> 3) * 1024 + blk * 8 + (lc & 7);
                s_gates[row][lc] = s + blstm[gc];
            }
            __syncthreads();
            // elementwise LSTM for this block's 8 units
            if (tid < 128) {
                int j = tid >> 3, uo = tid & 7;
                float gi = s_gates[j][uo],      gf = s_gates[j][8 + uo];
                float gg = s_gates[j][16 + uo], go = s_gates[j][24 + uo];
                float cp = g_c[par][s_nbhypo[j] * HH + blk * 8 + uo];
                float cc = sigf(gf) * cp + sigf(gi) * tanh_acc(gg);
                nc_s[j][uo] = cc;
                nh_s[j][uo] = sigf(go) * tanh_acc(cc);
            }
            __syncthreads();
            if (tid < 128) {
                int i2 = tid >> 3, uo = tid & 7, u = blk * 8 + uo;
                float hn, cn;
                if (s_isblank[i2]) {
                    hn = g_h[par][s_bsel[i2] * HH + u];
                    cn = g_c[par][s_bsel[i2] * HH + u];
                } else {
                    int ns = s_nsel[i2];
                    hn = nh_s[ns][uo]; cn = nc_s[ns][uo];
                }
                g_h[np][i2 * HH + u] = hn;
                g_c[np][i2 * HH + u] = cn;
            }
            if (tid < 64) {
                int i2 = tid >> 2, sl = blk * 4 + (tid & 3);
                int tok;
                if (s_isblank[i2]) {
                    tok = g_tokens[par][s_bsel[i2] * TT + sl];
                } else {
                    int ns = s_nsel[i2];
                    tok = (sl == t) ? s_nbtok[ns] : g_tokens[par][s_nbhypo[ns] * TT + sl];
                }
                g_tokens[np][i2 * TT + sl] = tok;
            }
        }
        gridbar();
    }

    // ================= epilogue =================
    if (blk == 0) {
        for (int e = tid; e < BB; e += NTHR) out[e] = g_scores2[0][e];
        for (int e = tid; e < BB * TT; e += NTHR) out[BB + e] = (float)g_tokens[0][e];
    }
}

// ---------------- host ----------------
extern "C" void kernel_launch(void* const* d_in, const int* in_sizes, int n_in,
                              void* d_out, int out_size) {
    const float* input   = (const float*)d_in[0];
    const float* enc_W   = (const float*)d_in[1];
    const float* enc_b   = (const float*)d_in[2];
    const float* embed   = (const float*)d_in[3];
    const float* Wx      = (const float*)d_in[4];
    const float* Wh      = (const float*)d_in[5];
    const float* b_lstm  = (const float*)d_in[6];
    const float* joint_W = (const float*)d_in[7];
    const float* joint_b = (const float*)d_in[8];
    (void)in_sizes; (void)n_in; (void)out_size;

    cudaFuncSetAttribute(rnnt_persist, cudaFuncAttributeMaxDynamicSharedMemorySize, DYN_SMEM);
    rnnt_persist<<<NBLK, NTHR, DYN_SMEM>>>(input, enc_W, enc_b, embed, Wx, Wh,
                                           b_lstm, joint_W, joint_b, (float*)d_out);
}